// round 6
// baseline (speedup 1.0000x reference)
#include <cuda_runtime.h>

typedef unsigned long long ull;
typedef unsigned int uint;

#define BB   64
#define CC   768
#define HW   24
#define NPIX 576
#define HID  768
#define NB   288        // 2 blocks/SM on 148 SMs -> co-resident
#define NT   512
#define NWARP (NB * 16) // 4608 warps
#define KSPL 12
#define KC   64
#define NCH  (BB * CC)  // 49152 channels

// ---------------- device scratch ----------------
__device__ __align__(16) ull   g_featp[BB * CC];
__device__ __align__(16) ull   g_actp[BB * HID];
__device__ __align__(16) float g_p1[KSPL][BB * HID];
__device__ __align__(16) float g_p2[KSPL][BB * HID];
__device__ int g_count = 0;
__device__ int g_sense = 0;

// ---------------- packed fp32 helpers ----------------
__device__ __forceinline__ ull ffma2(ull a, ull b, ull c) {
    ull d;
    asm("fma.rn.f32x2 %0, %1, %2, %3;" : "=l"(d) : "l"(a), "l"(b), "l"(c));
    return d;
}
__device__ __forceinline__ ull fadd2(ull a, ull b) {
    ull d;
    asm("add.rn.f32x2 %0, %1, %2;" : "=l"(d) : "l"(a), "l"(b));
    return d;
}
__device__ __forceinline__ ull dup2(float x) {
    ull d;
    asm("mov.b64 %0, {%1, %1};" : "=l"(d) : "f"(x));
    return d;
}
__device__ __forceinline__ ull pack2(float lo, float hi) {
    ull d;
    asm("mov.b64 %0, {%1, %2};" : "=l"(d) : "f"(lo), "f"(hi));
    return d;
}

__device__ __forceinline__ float hat_cdf(float t) {
    if (t <= -1.f) return 0.f;
    if (t <= 0.f) { float u = t + 1.f; return 0.5f * u * u; }
    if (t <= 1.f) { float u = 1.f - t; return 1.f - 0.5f * u * u; }
    return 1.f;
}

// ---------------- acq/rel grid barrier (CG-style) ----------------
__device__ __forceinline__ void grid_sync(int ls) {
    __syncthreads();
    if (threadIdx.x == 0) {
        int prev;
        asm volatile("atom.acq_rel.gpu.add.s32 %0, [%1], 1;"
                     : "=r"(prev) : "l"(&g_count) : "memory");
        if (prev == NB - 1) {
            g_count = 0;   // ordered before the release below
            asm volatile("st.release.gpu.s32 [%0], %1;"
                         :: "l"(&g_sense), "r"(ls) : "memory");
        } else {
            int s;
            do {
                asm volatile("ld.acquire.gpu.s32 %0, [%1];"
                             : "=r"(s) : "l"(&g_sense) : "memory");
            } while (s != ls);
        }
    }
    __syncthreads();
}

// ---------------- shared memory ----------------
__shared__ float s_wx[BB * 32];     // 8KB  (24 cols padded to 32; zeros beyond)
__shared__ float s_wy[BB * 16];     // 4KB  (wy * scale for rows hlo..hlo+15)
__shared__ int   s_hlo[BB];
__shared__ int   s_hlen[BB];
__shared__ __align__(16) ull s_A[32 * KC];   // 16KB GEMM A tile
__shared__ float s_red[16];

// ---------------- GEMM phase: 32 rows x 64 cols x KC ----------------
// bid -> x = bid%12 (col tile 64), y = (bid/12)&1 (row tile 32), z = bid/24 (k chunk)
__device__ __forceinline__ void gemm_phase(const ull* __restrict__ A,
                                           const float* __restrict__ W,
                                           float* __restrict__ P) {
    const int t = threadIdx.x;
    const int x = blockIdx.x % 12;
    const int y = (blockIdx.x / 12) & 1;
    const int z = blockIdx.x / 24;
    const int c0 = x * 64, r0 = y * 32, k0 = z * KC;

    // A tile: 32 rows x 64 k (ull) = 16KB; 512 threads x 4 ull
    {
        const int row = t >> 4, seg = (t & 15) * 4;
        const ull* src = A + (size_t)(r0 + row) * HID + k0 + seg;
        ull* dst = s_A + row * KC + seg;
        *(ulonglong2*)(dst + 0) = *(const ulonglong2*)(src + 0);
        *(ulonglong2*)(dst + 2) = *(const ulonglong2*)(src + 2);
    }
    __syncthreads();

    const int wid = t >> 5, lane = t & 31;
    const ull* ar = s_A + (wid * 2) * KC;
    const float* wptr = W + (size_t)k0 * HID + c0 + lane * 2;

    ull acc0 = 0ull, acc1 = 0ull;

    #pragma unroll 8
    for (int k = 0; k < KC; k += 2) {
        ull w0 = *(const ull*)(wptr + (size_t)k * HID);
        ull w1 = *(const ull*)(wptr + (size_t)(k + 1) * HID);
        ulonglong2 a0 = *(const ulonglong2*)(ar + 0 * KC + k);
        ulonglong2 a1 = *(const ulonglong2*)(ar + 1 * KC + k);
        acc0 = ffma2(a0.x, w0, acc0); acc0 = ffma2(a0.y, w1, acc0);
        acc1 = ffma2(a1.x, w0, acc1); acc1 = ffma2(a1.y, w1, acc1);
    }

    float* op = P + (size_t)z * (BB * HID) + (size_t)(r0 + wid * 2) * HID + c0 + lane * 2;
    *(ull*)(op + 0 * HID) = acc0;
    *(ull*)(op + 1 * HID) = acc1;
    __syncthreads();   // s_A reused by later phases
}

// ---------------- the single fused kernel ----------------
__global__ __launch_bounds__(NT, 2) void fused_kernel(
    const float* __restrict__ X,  const float* __restrict__ sb,
    const float* __restrict__ w1, const float* __restrict__ b1,
    const float* __restrict__ w2, const float* __restrict__ b2,
    const float* __restrict__ w3, const float* __restrict__ b3,
    float* __restrict__ out)
{
    const int bid = blockIdx.x;
    const int t = threadIdx.x;
    const int wid = t >> 5, lane = t & 31;

    // ======== phase 0a: tiny per-batch wx / wy tables (redundant per block) ====
    for (int e = t; e < BB * 32; e += NT) {
        const int b = e >> 5, w = e & 31;
        float x0 = sb[b * 4 + 0] * (float)HW;
        float x1 = sb[b * 4 + 2] * (float)HW;
        float v = 0.f;
        if (w < HW) v = hat_cdf(x1 - (float)w) - hat_cdf(x0 - (float)w);
        s_wx[e] = v;
    }
    for (int e = t; e < BB * 16; e += NT) {
        const int b = e >> 4, i = e & 15;
        float x0 = sb[b * 4 + 0] * (float)HW;
        float y0 = sb[b * 4 + 1] * (float)HW;
        float x1 = sb[b * 4 + 2] * (float)HW;
        float y1 = sb[b * 4 + 3] * (float)HW;
        float scale = 1.f / ((x1 - x0) * (y1 - y0));
        int hlo = max(0, (int)floorf(y0 - 1.f) + 1);
        int hhi = min(HW - 1, (int)ceilf(y1 + 1.f) - 1);
        if (i == 0) { s_hlo[b] = hlo; s_hlen[b] = hhi - hlo + 1; }
        int h = hlo + i;
        float v = 0.f;
        if (h <= hhi)
            v = (hat_cdf(y1 - (float)h) - hat_cdf(y0 - (float)h)) * scale;
        s_wy[e] = v;
    }
    __syncthreads();

    // ======== phase 0b: coalesced pooling. warp = 2 channels at a time ========
    {
        const int wg = bid * 16 + wid;
        for (int cg0 = wg; cg0 < NCH; cg0 += 2 * NWARP) {
            const int cg1 = cg0 + NWARP;
            const bool v1 = (cg1 < NCH);
            const int b0 = cg0 / CC;
            const int b1 = v1 ? (cg1 / CC) : 0;
            const float* p0 = X + (size_t)cg0 * NPIX + lane;
            const float* p1 = X + (size_t)(v1 ? cg1 : cg0) * NPIX + lane;
            const int hl0 = s_hlo[b0], n0 = s_hlen[b0];
            const int hl1 = s_hlo[b1], n1 = v1 ? s_hlen[b1] : 0;
            const int nm = max(n0, n1);

            float a0 = 0.f, a1 = 0.f;
            if (lane < HW) {
                #pragma unroll 4
                for (int i = 0; i < nm; i++) {
                    if (i < n0) a0 = fmaf(s_wy[b0 * 16 + i], p0[(hl0 + i) * HW], a0);
                    if (i < n1) a1 = fmaf(s_wy[b1 * 16 + i], p1[(hl1 + i) * HW], a1);
                }
                a0 *= s_wx[b0 * 32 + lane];
                a1 *= s_wx[b1 * 32 + lane];
            }
            ull pk = pack2(a0, a1);
            #pragma unroll
            for (int sh = 16; sh; sh >>= 1)
                pk = fadd2(pk, __shfl_xor_sync(0xffffffffu, pk, sh));
            if (lane == 0) {
                g_featp[cg0] = dup2(__uint_as_float((uint)pk));
                if (v1) g_featp[cg1] = dup2(__uint_as_float((uint)(pk >> 32)));
            }
        }
    }

    grid_sync(1);

    // ======== phase 1: GEMM 1 ========
    gemm_phase(g_featp, w1, &g_p1[0][0]);

    grid_sync(0);

    // ======== phase 2: combine partials + bias + relu + pack ========
    for (int idx = bid * NT + t; idx < NCH; idx += NB * NT) {
        const int c = idx % HID;
        float v = b1[c];
        #pragma unroll
        for (int z = 0; z < KSPL; z++) v += g_p1[z][idx];
        g_actp[idx] = dup2(fmaxf(v, 0.f));
    }

    grid_sync(1);

    // ======== phase 3: GEMM 2 ========
    gemm_phase(g_actp, w2, &g_p2[0][0]);

    grid_sync(0);

    // ======== phase 4: final combine + dot(w3) ========
    if (bid < BB) {
        float acc = 0.f;
        for (int k = t; k < HID; k += NT) {
            const int idx = bid * HID + k;
            float v = b2[k];
            #pragma unroll
            for (int z = 0; z < KSPL; z++) v += g_p2[z][idx];
            acc = fmaf(fmaxf(v, 0.f), w3[k], acc);
        }
        #pragma unroll
        for (int sh = 16; sh; sh >>= 1) acc += __shfl_xor_sync(0xffffffffu, acc, sh);
        if (lane == 0) s_red[wid] = acc;
        __syncthreads();
        if (t == 0) {
            float r = 0.f;
            #pragma unroll
            for (int j = 0; j < 16; j++) r += s_red[j];
            out[bid] = r + b3[0];
        }
    }
}

// ---------------- launch ----------------
extern "C" void kernel_launch(void* const* d_in, const int* in_sizes, int n_in,
                              void* d_out, int out_size) {
    const float* X  = (const float*)d_in[0];
    const float* sb = (const float*)d_in[1];
    const float* w1 = (const float*)d_in[2];
    const float* b1 = (const float*)d_in[3];
    const float* w2 = (const float*)d_in[4];
    const float* b2 = (const float*)d_in[5];
    const float* w3 = (const float*)d_in[6];
    const float* b3 = (const float*)d_in[7];
    float* out = (float*)d_out;

    fused_kernel<<<NB, NT>>>(X, sb, w1, b1, w2, b2, w3, b3, out);
}

// round 7
// speedup vs baseline: 1.3568x; 1.3568x over previous
#include <cuda_runtime.h>

typedef unsigned long long ull;
typedef unsigned int uint;

#define BB   64
#define CC   768
#define HW   24
#define NPIX 576
#define HID  768
#define NB   144        // blocks; <=148 so all co-resident
#define NT   512        // threads per block (16 warps)
#define NWARP (NB * 16) // 2304 warps
#define KSPL 12
#define KC   64
#define NCH  (BB * CC)
#define NIT8 (BB * 96)  // pool items: (batch, 8-channel group)
#define CHUNK 342

// ---------------- device scratch ----------------
__device__ __align__(16) ull   g_featp[BB * CC];
__device__ __align__(16) ull   g_actp[BB * HID];
__device__ __align__(16) float g_p1[KSPL][BB * HID];
__device__ __align__(16) float g_p2[KSPL][BB * HID];
__device__ int           g_count = 0;
__device__ volatile int  g_sense = 0;

// ---------------- packed fp32 helpers ----------------
__device__ __forceinline__ ull ffma2(ull a, ull b, ull c) {
    ull d;
    asm("fma.rn.f32x2 %0, %1, %2, %3;" : "=l"(d) : "l"(a), "l"(b), "l"(c));
    return d;
}
__device__ __forceinline__ ull fadd2(ull a, ull b) {
    ull d;
    asm("add.rn.f32x2 %0, %1, %2;" : "=l"(d) : "l"(a), "l"(b));
    return d;
}
__device__ __forceinline__ ull dup2(float x) {
    ull d;
    asm("mov.b64 %0, {%1, %1};" : "=l"(d) : "f"(x));
    return d;
}
__device__ __forceinline__ ull pack2(float lo, float hi) {
    ull d;
    asm("mov.b64 %0, {%1, %2};" : "=l"(d) : "f"(lo), "f"(hi));
    return d;
}
__device__ __forceinline__ float lo2(ull p) { return __uint_as_float((uint)p); }
__device__ __forceinline__ float hi2(ull p) { return __uint_as_float((uint)(p >> 32)); }

__device__ __forceinline__ float hat_cdf(float t) {
    if (t <= -1.f) return 0.f;
    if (t <= 0.f) { float u = t + 1.f; return 0.5f * u * u; }
    if (t <= 1.f) { float u = 1.f - t; return 1.f - 0.5f * u * u; }
    return 1.f;
}

// ---------------- grid barrier (R5-proven version) ----------------
__device__ __forceinline__ void grid_sync(int ls) {
    __syncthreads();
    __threadfence();
    if (threadIdx.x == 0) {
        if (atomicAdd(&g_count, 1) == NB - 1) {
            g_count = 0;
            __threadfence();
            g_sense = ls;
        } else {
            while (g_sense != ls) { }
        }
    }
    __syncthreads();
    __threadfence();
}

// ---------------- shared memory (static, 44.3 KB total) ----------------
__shared__ float s_wx[BB * 32];            // 8KB  (cols padded to 32, zeros)
__shared__ float s_wy[BB * 16];            // 4KB  (wy * scale)
__shared__ int   s_hlo[BB];
__shared__ int   s_hlen[BB];
__shared__ __align__(16) ull s_A[64 * KC]; // 32KB GEMM A tile
__shared__ float s_red[16];

// ---------------- GEMM phase: 64 rows x 64 cols x KC (R5 verbatim) ----------
__device__ __forceinline__ void gemm_phase(const ull* __restrict__ A,
                                           const float* __restrict__ W,
                                           float* __restrict__ P) {
    const int t = threadIdx.x;
    const int x = blockIdx.x % 12;
    const int z = blockIdx.x / 12;
    const int c0 = x * 64;
    const int k0 = z * KC;

    // A tile: 64 rows x 64 k (ull) = 32KB
    {
        const int row = t >> 3, seg = (t & 7) * 8;
        const ull* src = A + (size_t)row * HID + k0 + seg;
        ull* dst = s_A + row * KC + seg;
        #pragma unroll
        for (int j = 0; j < 8; j += 2)
            *(ulonglong2*)(dst + j) = *(const ulonglong2*)(src + j);
    }
    __syncthreads();

    const int wid = t >> 5, lane = t & 31;
    const ull* ar = s_A + (wid * 4) * KC;
    const float* wptr = W + (size_t)k0 * HID + c0 + lane * 2;

    ull acc0 = 0ull, acc1 = 0ull, acc2 = 0ull, acc3 = 0ull;

    #pragma unroll 4
    for (int k = 0; k < KC; k += 2) {
        ull w0 = *(const ull*)(wptr + (size_t)k * HID);
        ull w1 = *(const ull*)(wptr + (size_t)(k + 1) * HID);
        ulonglong2 a0 = *(const ulonglong2*)(ar + 0 * KC + k);
        ulonglong2 a1 = *(const ulonglong2*)(ar + 1 * KC + k);
        ulonglong2 a2 = *(const ulonglong2*)(ar + 2 * KC + k);
        ulonglong2 a3 = *(const ulonglong2*)(ar + 3 * KC + k);
        acc0 = ffma2(a0.x, w0, acc0); acc0 = ffma2(a0.y, w1, acc0);
        acc1 = ffma2(a1.x, w0, acc1); acc1 = ffma2(a1.y, w1, acc1);
        acc2 = ffma2(a2.x, w0, acc2); acc2 = ffma2(a2.y, w1, acc2);
        acc3 = ffma2(a3.x, w0, acc3); acc3 = ffma2(a3.y, w1, acc3);
    }

    float* op = P + (size_t)z * (BB * HID) + (size_t)(wid * 4) * HID + c0 + lane * 2;
    *(ull*)(op + 0 * HID) = acc0;
    *(ull*)(op + 1 * HID) = acc1;
    *(ull*)(op + 2 * HID) = acc2;
    *(ull*)(op + 3 * HID) = acc3;
    __syncthreads();
}

// ---------------- the single fused kernel ----------------
__global__ __launch_bounds__(NT, 1) void fused_kernel(
    const float* __restrict__ X,  const float* __restrict__ sb,
    const float* __restrict__ w1, const float* __restrict__ b1,
    const float* __restrict__ w2, const float* __restrict__ b2,
    const float* __restrict__ w3, const float* __restrict__ b3,
    float* __restrict__ out)
{
    const int bid = blockIdx.x;
    const int t = threadIdx.x;
    const int wid = t >> 5, lane = t & 31;

    // ======== phase 0a: tiny per-batch wx / wy tables ========
    for (int e = t; e < BB * 32; e += NT) {
        const int b = e >> 5, w = e & 31;
        float x0 = sb[b * 4 + 0] * (float)HW;
        float x1 = sb[b * 4 + 2] * (float)HW;
        float v = 0.f;
        if (w < HW) v = hat_cdf(x1 - (float)w) - hat_cdf(x0 - (float)w);
        s_wx[e] = v;
    }
    for (int e = t; e < BB * 16; e += NT) {
        const int b = e >> 4, i = e & 15;
        float x0 = sb[b * 4 + 0] * (float)HW;
        float y0 = sb[b * 4 + 1] * (float)HW;
        float x1 = sb[b * 4 + 2] * (float)HW;
        float y1 = sb[b * 4 + 3] * (float)HW;
        float scale = 1.f / ((x1 - x0) * (y1 - y0));
        int hlo = max(0, (int)floorf(y0 - 1.f) + 1);
        int hhi = min(HW - 1, (int)ceilf(y1 + 1.f) - 1);
        if (i == 0) { s_hlo[b] = hlo; s_hlen[b] = hhi - hlo + 1; }
        int h = hlo + i;
        float v = 0.f;
        if (h <= hhi)
            v = (hat_cdf(y1 - (float)h) - hat_cdf(y0 - (float)h)) * scale;
        s_wy[e] = v;
    }
    __syncthreads();

    // ======== phase 0b: row-coalesced pooling ========
    // item = (batch, 8 channels of that batch). warp lanes 0..23 = row cols.
    {
        const int wg = bid * 16 + wid;
        for (int it = wg; it < NIT8; it += NWARP) {
            const int b = it / 96;
            const int c0 = b * CC + (it - b * 96) * 8;
            const int hl = s_hlo[b], n = s_hlen[b];
            const float* base = X + (size_t)c0 * NPIX + hl * HW + lane;
            const float* wyp = s_wy + b * 16;

            float a0 = 0.f, a1 = 0.f, a2 = 0.f, a3 = 0.f;
            float a4 = 0.f, a5 = 0.f, a6 = 0.f, a7 = 0.f;
            if (lane < HW) {
                int off = 0;
                #pragma unroll 2
                for (int i = 0; i < n; i++, off += HW) {
                    const float wy = wyp[i];
                    const float* p = base + off;
                    a0 = fmaf(wy, __ldg(p + 0 * NPIX), a0);
                    a1 = fmaf(wy, __ldg(p + 1 * NPIX), a1);
                    a2 = fmaf(wy, __ldg(p + 2 * NPIX), a2);
                    a3 = fmaf(wy, __ldg(p + 3 * NPIX), a3);
                    a4 = fmaf(wy, __ldg(p + 4 * NPIX), a4);
                    a5 = fmaf(wy, __ldg(p + 5 * NPIX), a5);
                    a6 = fmaf(wy, __ldg(p + 6 * NPIX), a6);
                    a7 = fmaf(wy, __ldg(p + 7 * NPIX), a7);
                }
                const float wx = s_wx[b * 32 + lane];
                a0 *= wx; a1 *= wx; a2 *= wx; a3 *= wx;
                a4 *= wx; a5 *= wx; a6 *= wx; a7 *= wx;
            }
            ull p0 = pack2(a0, a1), p1 = pack2(a2, a3);
            ull p2 = pack2(a4, a5), p3 = pack2(a6, a7);
            #pragma unroll
            for (int sh = 16; sh; sh >>= 1) {
                p0 = fadd2(p0, __shfl_xor_sync(0xffffffffu, p0, sh));
                p1 = fadd2(p1, __shfl_xor_sync(0xffffffffu, p1, sh));
                p2 = fadd2(p2, __shfl_xor_sync(0xffffffffu, p2, sh));
                p3 = fadd2(p3, __shfl_xor_sync(0xffffffffu, p3, sh));
            }
            if (lane == 0) {
                g_featp[c0 + 0] = dup2(lo2(p0));
                g_featp[c0 + 1] = dup2(hi2(p0));
                g_featp[c0 + 2] = dup2(lo2(p1));
                g_featp[c0 + 3] = dup2(hi2(p1));
                g_featp[c0 + 4] = dup2(lo2(p2));
                g_featp[c0 + 5] = dup2(hi2(p2));
                g_featp[c0 + 6] = dup2(lo2(p3));
                g_featp[c0 + 7] = dup2(hi2(p3));
            }
        }
    }

    grid_sync(1);

    // ======== phase 1: GEMM 1 ========
    gemm_phase(g_featp, w1, &g_p1[0][0]);

    grid_sync(0);

    // ======== phase 2: combine partials + bias + relu + pack ========
    {
        const int s0 = bid * CHUNK;
        const int e0 = min(s0 + CHUNK, BB * HID);
        for (int idx = s0 + t; idx < e0; idx += NT) {
            const int c = idx % HID;
            float v = b1[c];
            #pragma unroll
            for (int z = 0; z < KSPL; z++) v += g_p1[z][idx];
            g_actp[idx] = dup2(fmaxf(v, 0.f));
        }
    }

    grid_sync(1);

    // ======== phase 3: GEMM 2 ========
    gemm_phase(g_actp, w2, &g_p2[0][0]);

    grid_sync(0);

    // ======== phase 4: final combine + dot(w3) ========
    if (bid < BB) {
        float acc = 0.f;
        for (int k = t; k < HID; k += NT) {
            const int idx = bid * HID + k;
            float v = b2[k];
            #pragma unroll
            for (int z = 0; z < KSPL; z++) v += g_p2[z][idx];
            acc = fmaf(fmaxf(v, 0.f), w3[k], acc);
        }
        #pragma unroll
        for (int sh = 16; sh; sh >>= 1) acc += __shfl_xor_sync(0xffffffffu, acc, sh);
        if (lane == 0) s_red[wid] = acc;
        __syncthreads();
        if (t == 0) {
            float r = 0.f;
            #pragma unroll
            for (int j = 0; j < 16; j++) r += s_red[j];
            out[bid] = r + b3[0];
        }
    }
}

// ---------------- launch ----------------
extern "C" void kernel_launch(void* const* d_in, const int* in_sizes, int n_in,
                              void* d_out, int out_size) {
    const float* X  = (const float*)d_in[0];
    const float* sb = (const float*)d_in[1];
    const float* w1 = (const float*)d_in[2];
    const float* b1 = (const float*)d_in[3];
    const float* w2 = (const float*)d_in[4];
    const float* b2 = (const float*)d_in[5];
    const float* w3 = (const float*)d_in[6];
    const float* b3 = (const float*)d_in[7];
    float* out = (float*)d_out;

    fused_kernel<<<NB, NT>>>(X, sb, w1, b1, w2, b2, w3, b3, out);
}

// round 8
// speedup vs baseline: 1.4664x; 1.0808x over previous
#include <cuda_runtime.h>

typedef unsigned long long ull;
typedef unsigned int uint;

#define BB   64
#define CC   768
#define HW   24
#define NPIX 576
#define HID  768
#define KSPL 24
#define KC   32         // KSPL*KC = 768
#define NCH  (BB * CC)
#define NIT8 (BB * 96)  // pool items: (batch, 8-channel group) = 6144

// ---------------- device scratch ----------------
__device__ __align__(16) ull   g_featp[BB * CC];
__device__ __align__(16) ull   g_actp[BB * HID];
__device__ __align__(16) float g_p1[KSPL][BB * HID];
__device__ __align__(16) float g_p2[KSPL][BB * HID];

// ---------------- packed fp32 helpers ----------------
__device__ __forceinline__ ull ffma2(ull a, ull b, ull c) {
    ull d;
    asm("fma.rn.f32x2 %0, %1, %2, %3;" : "=l"(d) : "l"(a), "l"(b), "l"(c));
    return d;
}
__device__ __forceinline__ ull fadd2(ull a, ull b) {
    ull d;
    asm("add.rn.f32x2 %0, %1, %2;" : "=l"(d) : "l"(a), "l"(b));
    return d;
}
__device__ __forceinline__ ull dup2(float x) {
    ull d;
    asm("mov.b64 %0, {%1, %1};" : "=l"(d) : "f"(x));
    return d;
}
__device__ __forceinline__ ull pack2(float lo, float hi) {
    ull d;
    asm("mov.b64 %0, {%1, %2};" : "=l"(d) : "f"(lo), "f"(hi));
    return d;
}
__device__ __forceinline__ float lo2(ull p) { return __uint_as_float((uint)p); }
__device__ __forceinline__ float hi2(ull p) { return __uint_as_float((uint)(p >> 32)); }

__device__ __forceinline__ float hat_cdf(float t) {
    if (t <= -1.f) return 0.f;
    if (t <= 0.f) { float u = t + 1.f; return 0.5f * u * u; }
    if (t <= 1.f) { float u = 1.f - t; return 1.f - 0.5f * u * u; }
    return 1.f;
}

// ================= kernel 1: pool (tables built per block) =================
// grid 768 x 256 thr: 8 warps/block, warp = one (batch, 8-channel) item.
__global__ __launch_bounds__(256) void pool_kernel(
    const float* __restrict__ X, const float* __restrict__ sb)
{
    __shared__ float s_wx[BB * 32];
    __shared__ float s_wy[BB * 16];
    __shared__ int   s_hlo[BB];
    __shared__ int   s_hlen[BB];

    const int t = threadIdx.x;
    const int wid = t >> 5, lane = t & 31;

    for (int e = t; e < BB * 32; e += 256) {
        const int b = e >> 5, w = e & 31;
        float x0 = sb[b * 4 + 0] * (float)HW;
        float x1 = sb[b * 4 + 2] * (float)HW;
        float v = 0.f;
        if (w < HW) v = hat_cdf(x1 - (float)w) - hat_cdf(x0 - (float)w);
        s_wx[e] = v;
    }
    for (int e = t; e < BB * 16; e += 256) {
        const int b = e >> 4, i = e & 15;
        float x0 = sb[b * 4 + 0] * (float)HW;
        float y0 = sb[b * 4 + 1] * (float)HW;
        float x1 = sb[b * 4 + 2] * (float)HW;
        float y1 = sb[b * 4 + 3] * (float)HW;
        float scale = 1.f / ((x1 - x0) * (y1 - y0));
        int hlo = max(0, (int)floorf(y0 - 1.f) + 1);
        int hhi = min(HW - 1, (int)ceilf(y1 + 1.f) - 1);
        if (i == 0) { s_hlo[b] = hlo; s_hlen[b] = hhi - hlo + 1; }
        int h = hlo + i;
        float v = 0.f;
        if (h <= hhi)
            v = (hat_cdf(y1 - (float)h) - hat_cdf(y0 - (float)h)) * scale;
        s_wy[e] = v;
    }
    __syncthreads();

    const int it = blockIdx.x * 8 + wid;
    if (it >= NIT8) return;
    const int b = it / 96;
    const int c0 = b * CC + (it - b * 96) * 8;
    const int hl = s_hlo[b], n = s_hlen[b];
    const float* base = X + (size_t)c0 * NPIX + hl * HW + lane;
    const float* wyp = s_wy + b * 16;

    float a0 = 0.f, a1 = 0.f, a2 = 0.f, a3 = 0.f;
    float a4 = 0.f, a5 = 0.f, a6 = 0.f, a7 = 0.f;
    if (lane < HW) {
        int off = 0;
        #pragma unroll 2
        for (int i = 0; i < n; i++, off += HW) {
            const float wy = wyp[i];
            const float* p = base + off;
            a0 = fmaf(wy, __ldg(p + 0 * NPIX), a0);
            a1 = fmaf(wy, __ldg(p + 1 * NPIX), a1);
            a2 = fmaf(wy, __ldg(p + 2 * NPIX), a2);
            a3 = fmaf(wy, __ldg(p + 3 * NPIX), a3);
            a4 = fmaf(wy, __ldg(p + 4 * NPIX), a4);
            a5 = fmaf(wy, __ldg(p + 5 * NPIX), a5);
            a6 = fmaf(wy, __ldg(p + 6 * NPIX), a6);
            a7 = fmaf(wy, __ldg(p + 7 * NPIX), a7);
        }
        const float wx = s_wx[b * 32 + lane];
        a0 *= wx; a1 *= wx; a2 *= wx; a3 *= wx;
        a4 *= wx; a5 *= wx; a6 *= wx; a7 *= wx;
    }
    ull p0 = pack2(a0, a1), p1 = pack2(a2, a3);
    ull p2 = pack2(a4, a5), p3 = pack2(a6, a7);
    #pragma unroll
    for (int sh = 16; sh; sh >>= 1) {
        p0 = fadd2(p0, __shfl_xor_sync(0xffffffffu, p0, sh));
        p1 = fadd2(p1, __shfl_xor_sync(0xffffffffu, p1, sh));
        p2 = fadd2(p2, __shfl_xor_sync(0xffffffffu, p2, sh));
        p3 = fadd2(p3, __shfl_xor_sync(0xffffffffu, p3, sh));
    }
    if (lane == 0) {
        g_featp[c0 + 0] = dup2(lo2(p0));
        g_featp[c0 + 1] = dup2(hi2(p0));
        g_featp[c0 + 2] = dup2(lo2(p1));
        g_featp[c0 + 3] = dup2(hi2(p1));
        g_featp[c0 + 4] = dup2(lo2(p2));
        g_featp[c0 + 5] = dup2(hi2(p2));
        g_featp[c0 + 6] = dup2(lo2(p3));
        g_featp[c0 + 7] = dup2(hi2(p3));
    }
}

// ================= kernel 2/4: GEMM (K-split 24, KC=32) =================
// grid (12, 24): x = 64-col tile, z = k-chunk. 512 thr; warp = 4 rows x 64 cols.
__global__ __launch_bounds__(512, 2) void gemm_kernel(
    const ull* __restrict__ A, const float* __restrict__ W,
    float* __restrict__ P)
{
    __shared__ __align__(16) ull s_A[64 * KC];   // 16KB

    const int t = threadIdx.x;
    const int c0 = blockIdx.x * 64;
    const int k0 = blockIdx.y * KC;

    // A tile: 64 rows x 32 k (ull); 512 threads x 4 ull
    {
        const int row = t >> 3, seg = (t & 7) * 4;
        const ull* src = A + (size_t)row * HID + k0 + seg;
        ull* dst = s_A + row * KC + seg;
        *(ulonglong2*)(dst + 0) = *(const ulonglong2*)(src + 0);
        *(ulonglong2*)(dst + 2) = *(const ulonglong2*)(src + 2);
    }
    __syncthreads();

    const int wid = t >> 5, lane = t & 31;
    const ull* ar = s_A + (wid * 4) * KC;
    const float* wptr = W + (size_t)k0 * HID + c0 + lane * 2;

    ull acc0 = 0ull, acc1 = 0ull, acc2 = 0ull, acc3 = 0ull;

    #pragma unroll 4
    for (int k = 0; k < KC; k += 2) {
        ull w0 = *(const ull*)(wptr + (size_t)k * HID);
        ull w1 = *(const ull*)(wptr + (size_t)(k + 1) * HID);
        ulonglong2 a0 = *(const ulonglong2*)(ar + 0 * KC + k);
        ulonglong2 a1 = *(const ulonglong2*)(ar + 1 * KC + k);
        ulonglong2 a2 = *(const ulonglong2*)(ar + 2 * KC + k);
        ulonglong2 a3 = *(const ulonglong2*)(ar + 3 * KC + k);
        acc0 = ffma2(a0.x, w0, acc0); acc0 = ffma2(a0.y, w1, acc0);
        acc1 = ffma2(a1.x, w0, acc1); acc1 = ffma2(a1.y, w1, acc1);
        acc2 = ffma2(a2.x, w0, acc2); acc2 = ffma2(a2.y, w1, acc2);
        acc3 = ffma2(a3.x, w0, acc3); acc3 = ffma2(a3.y, w1, acc3);
    }

    float* op = P + (size_t)blockIdx.y * (BB * HID)
              + (size_t)(wid * 4) * HID + c0 + lane * 2;
    *(ull*)(op + 0 * HID) = acc0;
    *(ull*)(op + 1 * HID) = acc1;
    *(ull*)(op + 2 * HID) = acc2;
    *(ull*)(op + 3 * HID) = acc3;
}

// ================= kernel 3: combine partials + bias + relu + pack =========
__global__ __launch_bounds__(512) void combine_kernel(const float* __restrict__ bias) {
    const int idx = blockIdx.x * 512 + threadIdx.x;   // 96*512 = 49152
    const int c = idx % HID;
    float v = bias[c];
    #pragma unroll
    for (int z = 0; z < KSPL; z++) v += g_p1[z][idx];
    g_actp[idx] = dup2(fmaxf(v, 0.f));
}

// ================= kernel 5: final combine + dot(w3) =================
__global__ __launch_bounds__(256) void final_kernel(
    const float* __restrict__ b2, const float* __restrict__ w3,
    const float* __restrict__ b3, float* __restrict__ out)
{
    __shared__ float red[8];
    const int b = blockIdx.x, t = threadIdx.x;
    const int wid = t >> 5, lane = t & 31;
    float acc = 0.f;
    #pragma unroll
    for (int k = t; k < HID; k += 256) {
        const int idx = b * HID + k;
        float v = b2[k];
        #pragma unroll
        for (int z = 0; z < KSPL; z++) v += g_p2[z][idx];
        acc = fmaf(fmaxf(v, 0.f), w3[k], acc);
    }
    #pragma unroll
    for (int sh = 16; sh; sh >>= 1) acc += __shfl_xor_sync(0xffffffffu, acc, sh);
    if (lane == 0) red[wid] = acc;
    __syncthreads();
    if (t == 0) {
        float r = red[0] + red[1] + red[2] + red[3] +
                  red[4] + red[5] + red[6] + red[7];
        out[b] = r + b3[0];
    }
}

// ---------------- launch ----------------
extern "C" void kernel_launch(void* const* d_in, const int* in_sizes, int n_in,
                              void* d_out, int out_size) {
    const float* X  = (const float*)d_in[0];
    const float* sb = (const float*)d_in[1];
    const float* w1 = (const float*)d_in[2];
    const float* b1 = (const float*)d_in[3];
    const float* w2 = (const float*)d_in[4];
    const float* b2 = (const float*)d_in[5];
    const float* w3 = (const float*)d_in[6];
    const float* b3 = (const float*)d_in[7];
    float* out = (float*)d_out;

    ull* featp; cudaGetSymbolAddress((void**)&featp, g_featp);
    ull* actp;  cudaGetSymbolAddress((void**)&actp,  g_actp);
    float* p1;  cudaGetSymbolAddress((void**)&p1, g_p1);
    float* p2;  cudaGetSymbolAddress((void**)&p2, g_p2);

    pool_kernel<<<768, 256>>>(X, sb);
    gemm_kernel<<<dim3(12, 24), 512>>>(featp, w1, p1);
    combine_kernel<<<96, 512>>>(b1);
    gemm_kernel<<<dim3(12, 24), 512>>>(actp, w2, p2);
    final_kernel<<<64, 256>>>(b2, w3, b3, out);
}